// round 2
// baseline (speedup 1.0000x reference)
#include <cuda_runtime.h>

// Problem constants
#define B_ 256
#define T_ 512          // TM1
#define N_ 256
#define H_ 256
#define G_ 1024         // 4*H
#define ENC_OFF ((size_t)B_ * T_ * N_)   // offset of input_encoded in d_out

// ---------------- device scratch (no cudaMalloc allowed) ----------------
__device__ float g_attn[B_ * N_];                    // softmax(x_scores)
__device__ float g_G1[(size_t)T_ * B_ * G_];         // weighted @ W_ih^T + biases, [t][b][j]
__device__ float g_hbuf[2][H_ * B_];                 // ping-pong hidden state, [h][b]
__device__ unsigned g_bar_count;
__device__ volatile unsigned g_bar_gen;

// ---------------- K1: x_scores + softmax -> attn, zero h buffer ----------------
__global__ void k_attn(const float* __restrict__ in, const float* __restrict__ attn_w) {
    __shared__ float wx[T_];
    __shared__ float red[N_];
    int b = blockIdx.x;
    int n = threadIdx.x;

    wx[n]       = attn_w[2 * H_ + n];
    wx[n + 256] = attn_w[2 * H_ + 256 + n];
    __syncthreads();

    const float* p = in + (size_t)b * T_ * N_ + n;
    float acc = 0.f;
#pragma unroll 8
    for (int t = 0; t < T_; ++t)
        acc = fmaf(p[(size_t)t * N_], wx[t], acc);

    // softmax over n (shift-invariance: h/c/attn_b terms cancel exactly)
    red[n] = acc;
    __syncthreads();
    for (int s = 128; s > 0; s >>= 1) {
        if (n < s) red[n] = fmaxf(red[n], red[n + s]);
        __syncthreads();
    }
    float mx = red[0];
    __syncthreads();
    float e = expf(acc - mx);
    red[n] = e;
    __syncthreads();
    for (int s = 128; s > 0; s >>= 1) {
        if (n < s) red[n] += red[n + s];
        __syncthreads();
    }
    g_attn[b * N_ + n] = e / red[0];

    // zero initial hidden state buffer (256 blocks * 256 threads == H_*B_)
    g_hbuf[0][b * N_ + n] = 0.f;
}

// ---------------- K2: weighted = attn * x -> output region 0 ----------------
__global__ void k_weighted(const float* __restrict__ in, float* __restrict__ out) {
    int blk = blockIdx.x;            // b*T_ + t
    int b = blk >> 9;
    int n = threadIdx.x;
    size_t idx = (size_t)blk * N_ + n;
    out[idx] = g_attn[b * N_ + n] * in[idx];
}

// ---------------- K3: G1[t*B+b][j] = weighted[b][t][:] . W_ih[j][:] + bias ----------------
#define TM 64
#define TN 64
#define TK 16
__global__ void k_gemm1(const float* __restrict__ Wih,
                        const float* __restrict__ b_ih,
                        const float* __restrict__ b_hh,
                        const float* __restrict__ wgt /* = d_out region 0 */) {
    __shared__ float As[TK][68];
    __shared__ float Bs[TK][68];
    int tid = threadIdx.x;                  // 256 threads
    int m0 = blockIdx.y * TM;               // row tile in m = t*256 + b space
    int j0 = blockIdx.x * TN;               // gate-column tile

    int r  = tid >> 2;                      // 0..63
    int c4 = (tid & 3) * 4;                 // 0,4,8,12
    int tx = tid & 15;                      // 0..15
    int ty = tid >> 4;                      // 0..15

    int m = m0 + r;
    int b = m & 255;
    int t = m >> 8;
    const float* arow = wgt + ((size_t)b * T_ + t) * N_;
    const float* brow = Wih + (size_t)(j0 + r) * N_;

    float acc[4][4] = {};

    for (int k0 = 0; k0 < N_; k0 += TK) {
        float4 av = *(const float4*)(arow + k0 + c4);
        float4 bv = *(const float4*)(brow + k0 + c4);
        __syncthreads();
        As[c4 + 0][r] = av.x; As[c4 + 1][r] = av.y;
        As[c4 + 2][r] = av.z; As[c4 + 3][r] = av.w;
        Bs[c4 + 0][r] = bv.x; Bs[c4 + 1][r] = bv.y;
        Bs[c4 + 2][r] = bv.z; Bs[c4 + 3][r] = bv.w;
        __syncthreads();
#pragma unroll
        for (int k = 0; k < TK; ++k) {
            float4 a = *(const float4*)&As[k][ty * 4];
            float4 w = *(const float4*)&Bs[k][tx * 4];
            float aa[4] = {a.x, a.y, a.z, a.w};
            float ww[4] = {w.x, w.y, w.z, w.w};
#pragma unroll
            for (int i = 0; i < 4; ++i)
#pragma unroll
                for (int j = 0; j < 4; ++j)
                    acc[i][j] = fmaf(aa[i], ww[j], acc[i][j]);
        }
    }

    float bs[4];
#pragma unroll
    for (int j = 0; j < 4; ++j)
        bs[j] = b_ih[j0 + tx * 4 + j] + b_hh[j0 + tx * 4 + j];
#pragma unroll
    for (int i = 0; i < 4; ++i) {
        size_t off = (size_t)(m0 + ty * 4 + i) * G_ + j0 + tx * 4;
        float4 o;
        o.x = acc[i][0] + bs[0];
        o.y = acc[i][1] + bs[1];
        o.z = acc[i][2] + bs[2];
        o.w = acc[i][3] + bs[3];
        *(float4*)(g_G1 + off) = o;
    }
}

// ---------------- K4: persistent recurrence ----------------
#define NBLK 128u

__device__ __forceinline__ void grid_sync() {
    __threadfence();
    __syncthreads();
    if (threadIdx.x == 0) {
        unsigned gen = g_bar_gen;
        if (atomicAdd(&g_bar_count, 1u) == NBLK - 1u) {
            g_bar_count = 0;
            __threadfence();
            g_bar_gen = gen + 1u;
        } else {
            while (g_bar_gen == gen) { __nanosleep(64); }
        }
        __threadfence();
    }
    __syncthreads();
}

__device__ __forceinline__ float sigf(float x) { return 1.f / (1.f + expf(-x)); }

// grid (8, 16): blockIdx.x -> 32-batch tile, blockIdx.y -> 16-hidden tile.
// 128 threads. Thread = (bg 0..7, hid 0..15), computes 4 batch x 4 gates,
// keeps its 4 c values in registers for the whole sequence.
__global__ void k_recur(const float* __restrict__ Whh, float* __restrict__ out_enc) {
    extern __shared__ float sm[];
    float*  Ws  = sm;                 // [256][16][4]  (k, hid, gate) = 64 KB
    float*  Hsf = sm + 256 * 64;      // [256][32]     (k, batch)     = 32 KB
    float4* Ws4 = (float4*)Ws;
    float4* Hs4 = (float4*)Hsf;

    int tid = threadIdx.x;            // 128
    int b0  = blockIdx.x * 32;
    int h0  = blockIdx.y * 16;

    // Load W_hh tile once; resident across all 512 steps.
    for (int idx = tid; idx < 256 * 64; idx += 128) {
        int k = idx >> 6;
        int col = idx & 63;
        int hid = col >> 2;
        int q = col & 3;
        Ws[idx] = Whh[(size_t)(q * H_ + h0 + hid) * N_ + k];
    }

    int bg  = tid >> 4;               // 0..7
    int hid = tid & 15;               // 0..15
    float creg[4] = {0.f, 0.f, 0.f, 0.f};
    __syncthreads();

    for (int t = 0; t < T_; ++t) {
        // init accumulators from precomputed G1 slice (global, read-only)
        float acc[4][4];
#pragma unroll
        for (int i = 0; i < 4; ++i) {
            int b = b0 + bg * 4 + i;
            const float* g1 = g_G1 + ((size_t)t * B_ + b) * G_ + h0 + hid;
            acc[0][i] = __ldcg(g1 + 0);
            acc[1][i] = __ldcg(g1 + 256);
            acc[2][i] = __ldcg(g1 + 512);
            acc[3][i] = __ldcg(g1 + 768);
        }

        // stage this CTA's h slice [256 k][32 b] (L2-coherent loads: other SMs wrote it)
        const float4* gh4 = (const float4*)g_hbuf[t & 1];
#pragma unroll 4
        for (int idx = tid; idx < 2048; idx += 128)
            Hs4[idx] = __ldcg(gh4 + (idx >> 3) * 64 + (b0 >> 2) + (idx & 7));
        __syncthreads();

        // gates += h @ W_hh^T   (2 LDS.128 + 16 FFMA per k)
#pragma unroll 4
        for (int k = 0; k < 256; ++k) {
            float4 h4 = Hs4[k * 8 + bg];
            float4 w4 = Ws4[k * 16 + hid];
            float hh[4] = {h4.x, h4.y, h4.z, h4.w};
            float ww[4] = {w4.x, w4.y, w4.z, w4.w};
#pragma unroll
            for (int q = 0; q < 4; ++q)
#pragma unroll
                for (int i = 0; i < 4; ++i)
                    acc[q][i] = fmaf(hh[i], ww[q], acc[q][i]);
        }

        // fused LSTM cell update + output store
        float* ghw = g_hbuf[(t + 1) & 1];
#pragma unroll
        for (int i = 0; i < 4; ++i) {
            int b = b0 + bg * 4 + i;
            float ig = sigf(acc[0][i]);
            float fg = sigf(acc[1][i]);
            float gg = tanhf(acc[2][i]);
            float og = sigf(acc[3][i]);
            float c = fmaf(fg, creg[i], ig * gg);
            creg[i] = c;
            float hn = og * tanhf(c);
            __stcg(&ghw[(h0 + hid) * B_ + b], hn);
            out_enc[((size_t)b * T_ + t) * H_ + h0 + hid] = hn;
        }

        if (t + 1 < T_) grid_sync();
    }
}

// ---------------- launch ----------------
extern "C" void kernel_launch(void* const* d_in, const int* in_sizes, int n_in,
                              void* d_out, int out_size) {
    const float* input  = (const float*)d_in[0];
    const float* W_ih   = (const float*)d_in[1];
    const float* W_hh   = (const float*)d_in[2];
    const float* b_ih   = (const float*)d_in[3];
    const float* b_hh   = (const float*)d_in[4];
    const float* attn_w = (const float*)d_in[5];
    float* out = (float*)d_out;

    cudaFuncSetAttribute(k_recur, cudaFuncAttributeMaxDynamicSharedMemorySize, 98304);

    // K1: attention weights (+ zero h state)
    k_attn<<<B_, N_>>>(input, attn_w);
    // K2: weighted input -> output region 0
    k_weighted<<<B_ * T_, N_>>>(input, out);
    // K3: big input-gate GEMM into scratch (reads output region 0)
    dim3 g3(G_ / TN, (T_ * B_) / TM);
    k_gemm1<<<g3, 256>>>(W_ih, b_ih, b_hh, out);
    // K4: persistent recurrence -> output region 1
    dim3 g4(8, 16);
    k_recur<<<g4, 128, 98304>>>(W_hh, out + ENC_OFF);
}

// round 3
// speedup vs baseline: 1.3737x; 1.3737x over previous
#include <cuda_runtime.h>

// Problem constants
#define B_ 256
#define T_ 512          // TM1
#define N_ 256
#define H_ 256
#define G_ 1024         // 4*H
#define ENC_OFF ((size_t)B_ * T_ * N_)   // offset of input_encoded in d_out

// ---------------- device scratch (no cudaMalloc allowed) ----------------
__device__ float g_attn[B_ * N_];                    // softmax(x_scores)
__device__ float g_G1[(size_t)T_ * B_ * G_];         // weighted @ W_ih^T + biases, [t][b][j]
__device__ float g_hbuf[2][H_ * B_];                 // ping-pong hidden state, [h][b]
__device__ unsigned g_bar_count;
__device__ volatile unsigned g_bar_gen;

// ---------------- packed fp32x2 helpers (full fp32 precision, 2 MACs/instr) ----
#define FMA2(d, a, b) asm("fma.rn.f32x2 %0, %1, %2, %0;" : "+l"(d) : "l"(a), "l"(b))

__device__ __forceinline__ unsigned long long pk2(float lo, float hi) {
    unsigned long long r;
    asm("mov.b64 %0, {%1, %2};" : "=l"(r) : "f"(lo), "f"(hi));
    return r;
}
__device__ __forceinline__ void upk2(unsigned long long v, float& lo, float& hi) {
    asm("mov.b64 {%0, %1}, %2;" : "=f"(lo), "=f"(hi) : "l"(v));
}

__device__ __forceinline__ float sigf(float x) {
    return __fdividef(1.f, 1.f + __expf(-x));
}
__device__ __forceinline__ float tanhfast(float x) {
    return __fdividef(2.f, 1.f + __expf(-2.f * x)) - 1.f;
}

// ---------------- K1: x_scores + softmax -> attn, zero h buffer ----------------
__global__ void k_attn(const float* __restrict__ in, const float* __restrict__ attn_w) {
    __shared__ float wx[T_];
    __shared__ float red[N_];
    int b = blockIdx.x;
    int n = threadIdx.x;

    wx[n]       = attn_w[2 * H_ + n];
    wx[n + 256] = attn_w[2 * H_ + 256 + n];
    __syncthreads();

    const float* p = in + (size_t)b * T_ * N_ + n;
    float acc = 0.f;
#pragma unroll 8
    for (int t = 0; t < T_; ++t)
        acc = fmaf(p[(size_t)t * N_], wx[t], acc);

    // softmax over n (shift-invariance: h/c/attn_b terms cancel exactly)
    red[n] = acc;
    __syncthreads();
    for (int s = 128; s > 0; s >>= 1) {
        if (n < s) red[n] = fmaxf(red[n], red[n + s]);
        __syncthreads();
    }
    float mx = red[0];
    __syncthreads();
    float e = expf(acc - mx);
    red[n] = e;
    __syncthreads();
    for (int s = 128; s > 0; s >>= 1) {
        if (n < s) red[n] += red[n + s];
        __syncthreads();
    }
    g_attn[b * N_ + n] = e / red[0];

    // zero initial hidden state buffer (256 blocks * 256 threads == H_*B_)
    g_hbuf[0][b * N_ + n] = 0.f;
}

// ---------------- K2: weighted = attn * x -> output region 0 ----------------
__global__ void k_weighted(const float* __restrict__ in, float* __restrict__ out) {
    int blk = blockIdx.x;            // b*T_ + t
    int b = blk >> 9;
    int n = threadIdx.x;
    size_t idx = (size_t)blk * N_ + n;
    out[idx] = g_attn[b * N_ + n] * in[idx];
}

// ---------------- K3: G1[t*B+b][j] = weighted[b][t][:] . W_ih[j][:] + bias ----
// 64x64x(K=256) tile per CTA, 256 threads, fp32x2 packed FMAs.
#define TM 64
#define TN 64
#define TK 16
__global__ void __launch_bounds__(256) k_gemm1(
        const float* __restrict__ Wih,
        const float* __restrict__ b_ih,
        const float* __restrict__ b_hh,
        const float* __restrict__ wgt /* = d_out region 0 */) {
    // A stored DUPLICATED ((a,a) pairs) so FMA2 reads it straight from LDS
    __shared__ __align__(16) float As[TK * 132];   // [k][2*64 + pad]
    __shared__ __align__(16) float Bs[TK * 68];    // [k][64 + pad]

    int tid = threadIdx.x;                  // 256 threads
    int m0 = blockIdx.y * TM;               // row tile in m = t*256 + b space
    int j0 = blockIdx.x * TN;               // gate-column tile

    int r  = tid >> 2;                      // 0..63
    int c4 = (tid & 3) * 4;                 // 0,4,8,12
    int tx = tid & 15;                      // 0..15
    int ty = tid >> 4;                      // 0..15

    int m = m0 + r;
    int b = m & 255;
    int t = m >> 8;
    const float* arow = wgt + ((size_t)b * T_ + t) * N_;
    const float* brow = Wih + (size_t)(j0 + r) * N_;

    unsigned long long* As8 = (unsigned long long*)As;
    const ulonglong2* As2 = (const ulonglong2*)As;
    const ulonglong2* Bs2 = (const ulonglong2*)Bs;

    unsigned long long acc0[4] = {0ull, 0ull, 0ull, 0ull};  // (j0..j1) pairs
    unsigned long long acc1[4] = {0ull, 0ull, 0ull, 0ull};  // (j2..j3) pairs

    for (int k0 = 0; k0 < N_; k0 += TK) {
        float4 av = *(const float4*)(arow + k0 + c4);
        float4 bv = *(const float4*)(brow + k0 + c4);
        __syncthreads();
        As8[(c4 + 0) * 66 + r] = pk2(av.x, av.x);
        As8[(c4 + 1) * 66 + r] = pk2(av.y, av.y);
        As8[(c4 + 2) * 66 + r] = pk2(av.z, av.z);
        As8[(c4 + 3) * 66 + r] = pk2(av.w, av.w);
        Bs[(c4 + 0) * 68 + r] = bv.x;
        Bs[(c4 + 1) * 68 + r] = bv.y;
        Bs[(c4 + 2) * 68 + r] = bv.z;
        Bs[(c4 + 3) * 68 + r] = bv.w;
        __syncthreads();
#pragma unroll
        for (int k = 0; k < TK; ++k) {
            ulonglong2 w   = Bs2[k * 17 + tx];           // (w0,w1),(w2,w3)
            ulonglong2 a01 = As2[k * 33 + ty * 2];       // (a0,a0),(a1,a1)
            ulonglong2 a23 = As2[k * 33 + ty * 2 + 1];   // (a2,a2),(a3,a3)
            FMA2(acc0[0], a01.x, w.x); FMA2(acc1[0], a01.x, w.y);
            FMA2(acc0[1], a01.y, w.x); FMA2(acc1[1], a01.y, w.y);
            FMA2(acc0[2], a23.x, w.x); FMA2(acc1[2], a23.x, w.y);
            FMA2(acc0[3], a23.y, w.x); FMA2(acc1[3], a23.y, w.y);
        }
    }

    float bs[4];
#pragma unroll
    for (int j = 0; j < 4; ++j)
        bs[j] = b_ih[j0 + tx * 4 + j] + b_hh[j0 + tx * 4 + j];
#pragma unroll
    for (int i = 0; i < 4; ++i) {
        float o0, o1, o2, o3;
        upk2(acc0[i], o0, o1);
        upk2(acc1[i], o2, o3);
        size_t off = (size_t)(m0 + ty * 4 + i) * G_ + j0 + tx * 4;
        float4 o;
        o.x = o0 + bs[0];
        o.y = o1 + bs[1];
        o.z = o2 + bs[2];
        o.w = o3 + bs[3];
        *(float4*)(g_G1 + off) = o;
    }
}

// ---------------- K4: persistent recurrence ----------------
#define NBLK 128u

__device__ __forceinline__ void grid_sync() {
    __threadfence();
    __syncthreads();
    if (threadIdx.x == 0) {
        unsigned gen = g_bar_gen;
        if (atomicAdd(&g_bar_count, 1u) == NBLK - 1u) {
            g_bar_count = 0;
            __threadfence();
            g_bar_gen = gen + 1u;
        } else {
            while (g_bar_gen == gen) { __nanosleep(64); }
        }
        __threadfence();
    }
    __syncthreads();
}

// grid (8, 16): blockIdx.x -> 32-batch tile, blockIdx.y -> 16-hidden tile.
// 128 threads. Thread = (bg 0..7, hid 0..15), 4 batches x 4 gates via fp32x2.
// SMEM: Ws [k][hid][4 gates] (64KB, gate-paired for FMA2) +
//       Hs [k][32 b duplicated] (64KB, (h,h) pairs for FMA2).
__global__ void __launch_bounds__(128, 1) k_recur(
        const float* __restrict__ Whh, float* __restrict__ out_enc) {
    extern __shared__ float sm[];
    float* Ws = sm;                   // 16384 floats
    float* Hs = sm + 16384;           // 16384 floats (duplicated h)
    const ulonglong2* Ws2 = (const ulonglong2*)Ws;
    const ulonglong2* Hs2 = (const ulonglong2*)Hs;
    float4* Hs4 = (float4*)Hs;

    int tid = threadIdx.x;            // 128
    int b0  = blockIdx.x * 32;
    int h0  = blockIdx.y * 16;

    // Load W_hh tile once; resident across all 512 steps. layout [k][hid][q]
    for (int idx = tid; idx < 16384; idx += 128) {
        int k = idx >> 6;
        int col = idx & 63;
        int hh = col >> 2;
        int q = col & 3;
        Ws[idx] = Whh[(size_t)(q * H_ + h0 + hh) * N_ + k];
    }

    int bg  = tid >> 4;               // 0..7
    int hid = tid & 15;               // 0..15
    float creg[4] = {0.f, 0.f, 0.f, 0.f};
    __syncthreads();

    for (int t = 0; t < T_; ++t) {
        // init packed accumulators from precomputed G1 slice
        unsigned long long accA[4], accB[4];   // (i,f) and (g,o) gate pairs
#pragma unroll
        for (int i = 0; i < 4; ++i) {
            int b = b0 + bg * 4 + i;
            const float* g1 = g_G1 + ((size_t)t * B_ + b) * G_ + h0 + hid;
            accA[i] = pk2(__ldcg(g1 + 0),   __ldcg(g1 + 256));
            accB[i] = pk2(__ldcg(g1 + 512), __ldcg(g1 + 768));
        }

        // stage this CTA's h slice [256 k][32 b] DUPLICATED for FMA2
        const float4* gh4 = (const float4*)g_hbuf[t & 1];
#pragma unroll
        for (int it = 0; it < 16; ++it) {
            int idx = tid + it * 128;         // 0..2047
            int k = idx >> 3;
            int j = idx & 7;
            float4 v = __ldcg(gh4 + k * 64 + (b0 >> 2) + j);
            Hs4[k * 16 + j * 2]     = make_float4(v.x, v.x, v.y, v.y);
            Hs4[k * 16 + j * 2 + 1] = make_float4(v.z, v.z, v.w, v.w);
        }
        __syncthreads();

        // gates += h @ W_hh^T   (3 LDS.128 + 8 FMA2 per k)
        const ulonglong2* wp = Ws2 + hid;
        const ulonglong2* hp = Hs2 + bg * 2;
#pragma unroll 8
        for (int k = 0; k < 256; ++k) {
            ulonglong2 w   = wp[k * 16];      // (w_i,w_f),(w_g,w_o)
            ulonglong2 h01 = hp[k * 16];      // (h0,h0),(h1,h1)
            ulonglong2 h23 = hp[k * 16 + 1];  // (h2,h2),(h3,h3)
            FMA2(accA[0], h01.x, w.x); FMA2(accB[0], h01.x, w.y);
            FMA2(accA[1], h01.y, w.x); FMA2(accB[1], h01.y, w.y);
            FMA2(accA[2], h23.x, w.x); FMA2(accB[2], h23.x, w.y);
            FMA2(accA[3], h23.y, w.x); FMA2(accB[3], h23.y, w.y);
        }

        // fused LSTM cell update + output store
        float* ghw = g_hbuf[(t + 1) & 1];
#pragma unroll
        for (int i = 0; i < 4; ++i) {
            int b = b0 + bg * 4 + i;
            float gi, gf, gg, go;
            upk2(accA[i], gi, gf);
            upk2(accB[i], gg, go);
            float ig = sigf(gi);
            float fg = sigf(gf);
            float g_ = tanhfast(gg);
            float og = sigf(go);
            float c = fmaf(fg, creg[i], ig * g_);
            creg[i] = c;
            float hn = og * tanhfast(c);
            __stcg(&ghw[(h0 + hid) * B_ + b], hn);
            out_enc[((size_t)b * T_ + t) * H_ + h0 + hid] = hn;
        }

        if (t + 1 < T_) grid_sync();
    }
}

// ---------------- launch ----------------
extern "C" void kernel_launch(void* const* d_in, const int* in_sizes, int n_in,
                              void* d_out, int out_size) {
    const float* input  = (const float*)d_in[0];
    const float* W_ih   = (const float*)d_in[1];
    const float* W_hh   = (const float*)d_in[2];
    const float* b_ih   = (const float*)d_in[3];
    const float* b_hh   = (const float*)d_in[4];
    const float* attn_w = (const float*)d_in[5];
    float* out = (float*)d_out;

    cudaFuncSetAttribute(k_recur, cudaFuncAttributeMaxDynamicSharedMemorySize, 131072);

    // K1: attention weights (+ zero h state)
    k_attn<<<B_, N_>>>(input, attn_w);
    // K2: weighted input -> output region 0
    k_weighted<<<B_ * T_, N_>>>(input, out);
    // K3: big input-gate GEMM into scratch (reads output region 0)
    dim3 g3(G_ / TN, (T_ * B_) / TM);
    k_gemm1<<<g3, 256>>>(W_ih, b_ih, b_hh, out);
    // K4: persistent recurrence -> output region 1
    dim3 g4(8, 16);
    k_recur<<<g4, 128, 131072>>>(W_hh, out + ENC_OFF);
}

// round 6
// speedup vs baseline: 1.7212x; 1.2530x over previous
#include <cuda_runtime.h>
#include <cuda_bf16.h>
#include <cstdint>

// Problem constants
#define B_ 256
#define T_ 512          // TM1
#define N_ 256
#define H_ 256
#define G_ 1024         // 4*H
#define ENC_OFF ((size_t)B_ * T_ * N_)   // offset of input_encoded in d_out

// ---------------- device scratch (no cudaMalloc allowed) ----------------
__device__ float g_attn[B_ * N_];                      // softmax(x_scores)
__device__ float g_G1[(size_t)T_ * B_ * G_];           // gates pre-recurrence, [m=t*B+b][j]
__device__ float g_hbuf[2][H_ * B_];                   // ping-pong hidden state, [h][b]
__device__ __nv_bfloat16 g_Ahi[(size_t)T_ * B_ * N_];  // weighted, bf16 hi
__device__ __nv_bfloat16 g_Alo[(size_t)T_ * B_ * N_];  // weighted, bf16 lo
__device__ __nv_bfloat16 g_Bhi[G_ * N_];               // W_ih, bf16 hi
__device__ __nv_bfloat16 g_Blo[G_ * N_];               // W_ih, bf16 lo
__device__ unsigned g_bar_count;
__device__ volatile unsigned g_bar_gen;

// ---------------- packed fp32x2 helpers ----------------
#define FMA2(d, a, b) asm("fma.rn.f32x2 %0, %1, %2, %0;" : "+l"(d) : "l"(a), "l"(b))

__device__ __forceinline__ unsigned long long pk2(float lo, float hi) {
    unsigned long long r;
    asm("mov.b64 %0, {%1, %2};" : "=l"(r) : "f"(lo), "f"(hi));
    return r;
}
__device__ __forceinline__ void upk2(unsigned long long v, float& lo, float& hi) {
    asm("mov.b64 {%0, %1}, %2;" : "=f"(lo), "=f"(hi) : "l"(v));
}
__device__ __forceinline__ float sigf(float x) {
    return __fdividef(1.f, 1.f + __expf(-x));
}
__device__ __forceinline__ float tanhfast(float x) {
    return __fdividef(2.f, 1.f + __expf(-2.f * x)) - 1.f;
}
__device__ __forceinline__ uint32_t smem_to_u32(const void* p) {
    uint32_t a;
    asm("{ .reg .u64 t; cvta.to.shared.u64 t, %1; cvt.u32.u64 %0, t; }" : "=r"(a) : "l"(p));
    return a;
}

// ---------------- K1: x_scores + softmax -> attn, zero h buffer ----------------
__global__ void k_attn(const float* __restrict__ in, const float* __restrict__ attn_w) {
    __shared__ float wx[T_];
    __shared__ float red[N_];
    int b = blockIdx.x;
    int n = threadIdx.x;

    wx[n]       = attn_w[2 * H_ + n];
    wx[n + 256] = attn_w[2 * H_ + 256 + n];
    __syncthreads();

    const float* p = in + (size_t)b * T_ * N_ + n;
    float acc = 0.f;
#pragma unroll 8
    for (int t = 0; t < T_; ++t)
        acc = fmaf(p[(size_t)t * N_], wx[t], acc);

    red[n] = acc;
    __syncthreads();
    for (int s = 128; s > 0; s >>= 1) {
        if (n < s) red[n] = fmaxf(red[n], red[n + s]);
        __syncthreads();
    }
    float mx = red[0];
    __syncthreads();
    float e = expf(acc - mx);
    red[n] = e;
    __syncthreads();
    for (int s = 128; s > 0; s >>= 1) {
        if (n < s) red[n] += red[n + s];
        __syncthreads();
    }
    g_attn[b * N_ + n] = e / red[0];
    g_hbuf[0][b * N_ + n] = 0.f;
}

// ---------------- K2: weighted = attn * x -> out region 0 + bf16 hi/lo ---------
__global__ void k_weighted(const float* __restrict__ in, float* __restrict__ out) {
    int blk = blockIdx.x;            // b*T_ + t
    int b = blk >> 9;
    int t = blk & 511;
    int n = threadIdx.x;
    size_t idx = (size_t)blk * N_ + n;
    float w = g_attn[b * N_ + n] * in[idx];
    out[idx] = w;
    size_t m = (size_t)t * B_ + b;   // GEMM row index
    __nv_bfloat16 hi = __float2bfloat16(w);
    __nv_bfloat16 lo = __float2bfloat16(w - __bfloat162float(hi));
    g_Ahi[m * N_ + n] = hi;
    g_Alo[m * N_ + n] = lo;
}

// ---------------- K2b: W_ih -> bf16 hi/lo ----------------
__global__ void k_convB(const float* __restrict__ Wih) {
    int j = blockIdx.x;
    int k = threadIdx.x;
    float v = Wih[(size_t)j * N_ + k];
    __nv_bfloat16 hi = __float2bfloat16(v);
    __nv_bfloat16 lo = __float2bfloat16(v - __bfloat162float(hi));
    g_Bhi[j * N_ + k] = hi;
    g_Blo[j * N_ + k] = lo;
}

// ---------------- K3: mma.sync bf16 split GEMM ----------------
// D[128m x 128n] per CTA; effective K = 768 = 3 terms x 256:
//   term0: Ahi*Bhi, term1: Alo*Bhi, term2: Ahi*Blo   (lo*lo dropped)
// 8 warps as 2(m) x 4(n); warp tile 64x32; m16n8k16 HMMA.
#define LDM_X4(r0, r1, r2, r3, a) \
    asm volatile("ldmatrix.sync.aligned.m8n8.x4.shared.b16 {%0,%1,%2,%3}, [%4];" \
                 : "=r"(r0), "=r"(r1), "=r"(r2), "=r"(r3) : "r"(a))
#define MMA16816(c, a, b) \
    asm volatile("mma.sync.aligned.m16n8k16.row.col.f32.bf16.bf16.f32 " \
                 "{%0,%1,%2,%3}, {%4,%5,%6,%7}, {%8,%9}, {%0,%1,%2,%3};" \
                 : "+f"((c)[0]), "+f"((c)[1]), "+f"((c)[2]), "+f"((c)[3]) \
                 : "r"((a)[0]), "r"((a)[1]), "r"((a)[2]), "r"((a)[3]), "r"((b)[0]), "r"((b)[1]))

__global__ void __launch_bounds__(256) k_gemm_mma(
        const float* __restrict__ b_ih, const float* __restrict__ b_hh) {
    __shared__ __align__(16) __nv_bfloat16 As[128 * 64];   // 16 KB, swizzled
    __shared__ __align__(16) __nv_bfloat16 Bs[128 * 64];   // 16 KB, swizzled
    __shared__ float bias_s[128];

    int tid = threadIdx.x;
    int wid = tid >> 5;
    int lane = tid & 31;
    int nt = blockIdx.x;             // 0..7  gate tile
    int mt = blockIdx.y;             // 0..1023 m tile
    int j0 = nt * 128;
    int wm = wid >> 2;               // 0..1
    int wn = wid & 3;                // 0..3

    if (tid < 128) bias_s[tid] = b_ih[j0 + tid] + b_hh[j0 + tid];

    uint32_t as_base = smem_to_u32(As);
    uint32_t bs_base = smem_to_u32(Bs);

    // ldmatrix lane-dependent precomputation
    int a_r15 = lane & 15;                 // row within 16-tile
    int a_kh  = lane >> 4;                 // 0/1 -> k half
    int b_row = ((lane & 16) >> 1) + (lane & 7);   // 16 n-rows across lane quads
    int b_kh  = (lane >> 3) & 1;           // 0/1 -> k half

    float acc[4][4][4];
#pragma unroll
    for (int i = 0; i < 4; ++i)
#pragma unroll
        for (int j = 0; j < 4; ++j)
#pragma unroll
            for (int q = 0; q < 4; ++q) acc[i][j][q] = 0.f;

    const __nv_bfloat16* a_srcs[3] = {g_Ahi, g_Alo, g_Ahi};
    const __nv_bfloat16* b_srcs[3] = {g_Bhi, g_Bhi, g_Blo};

    for (int ch = 0; ch < 12; ++ch) {
        int term = ch >> 2;
        int kk0 = (ch & 3) * 64;
        const uint4* gA = (const uint4*)(a_srcs[term] + (size_t)mt * 128 * N_ + kk0);
        const uint4* gB = (const uint4*)(b_srcs[term] + (size_t)j0 * N_ + kk0);
        uint4* sA = (uint4*)As;
        uint4* sB = (uint4*)Bs;
        __syncthreads();
#pragma unroll
        for (int it = 0; it < 4; ++it) {
            int idx = tid + it * 256;        // 0..1023
            int r = idx >> 3;
            int kg = idx & 7;
            sA[r * 8 + (kg ^ (r & 7))] = gA[r * 32 + kg];
            sB[r * 8 + (kg ^ (r & 7))] = gB[r * 32 + kg];
        }
        __syncthreads();

#pragma unroll
        for (int ks = 0; ks < 4; ++ks) {
            uint32_t afr[4][4];
            uint32_t bfr[4][2];
#pragma unroll
            for (int tm = 0; tm < 4; ++tm) {
                int row = wm * 64 + tm * 16 + a_r15;
                int c = (2 * ks + a_kh) ^ (a_r15 & 7);
                uint32_t addr = as_base + (uint32_t)(row * 64 + c * 8) * 2u;
                LDM_X4(afr[tm][0], afr[tm][1], afr[tm][2], afr[tm][3], addr);
            }
#pragma unroll
            for (int tn2 = 0; tn2 < 2; ++tn2) {
                int row = wn * 32 + tn2 * 16 + b_row;
                int c = (2 * ks + b_kh) ^ (b_row & 7);
                uint32_t addr = bs_base + (uint32_t)(row * 64 + c * 8) * 2u;
                uint32_t r0, r1, r2, r3;
                LDM_X4(r0, r1, r2, r3, addr);
                bfr[tn2 * 2 + 0][0] = r0; bfr[tn2 * 2 + 0][1] = r1;
                bfr[tn2 * 2 + 1][0] = r2; bfr[tn2 * 2 + 1][1] = r3;
            }
#pragma unroll
            for (int tm = 0; tm < 4; ++tm)
#pragma unroll
                for (int tn = 0; tn < 4; ++tn)
                    MMA16816(acc[tm][tn], afr[tm], bfr[tn]);
        }
    }

    // epilogue: add bias, write g_G1
    int qr = lane >> 2;              // 0..7 row-in-8
    int qc = (lane & 3) * 2;         // col pair base
#pragma unroll
    for (int tm = 0; tm < 4; ++tm) {
#pragma unroll
        for (int tn = 0; tn < 4; ++tn) {
            int colt = wn * 32 + tn * 8 + qc;       // 0..127 within tile
            size_t m0 = (size_t)mt * 128 + wm * 64 + tm * 16 + qr;
            float bx = bias_s[colt], by = bias_s[colt + 1];
            float2 v0 = make_float2(acc[tm][tn][0] + bx, acc[tm][tn][1] + by);
            float2 v1 = make_float2(acc[tm][tn][2] + bx, acc[tm][tn][3] + by);
            *(float2*)(g_G1 + m0 * G_ + j0 + colt) = v0;
            *(float2*)(g_G1 + (m0 + 8) * G_ + j0 + colt) = v1;
        }
    }
}

// ---------------- K4: persistent recurrence (EXACT round-3 proven version) ----
#define NBLK 128u

__device__ __forceinline__ void grid_sync() {
    __threadfence();
    __syncthreads();
    if (threadIdx.x == 0) {
        unsigned gen = g_bar_gen;
        if (atomicAdd(&g_bar_count, 1u) == NBLK - 1u) {
            g_bar_count = 0;
            __threadfence();
            g_bar_gen = gen + 1u;
        } else {
            while (g_bar_gen == gen) { __nanosleep(64); }
        }
        __threadfence();
    }
    __syncthreads();
}

__global__ void __launch_bounds__(128, 1) k_recur(
        const float* __restrict__ Whh, float* __restrict__ out_enc) {
    extern __shared__ float sm[];
    float* Ws = sm;                   // 16384 floats
    float* Hs = sm + 16384;           // 16384 floats (duplicated h)
    const ulonglong2* Ws2 = (const ulonglong2*)Ws;
    const ulonglong2* Hs2 = (const ulonglong2*)Hs;
    float4* Hs4 = (float4*)Hs;

    int tid = threadIdx.x;            // 128
    int b0  = blockIdx.x * 32;
    int h0  = blockIdx.y * 16;

    for (int idx = tid; idx < 16384; idx += 128) {
        int k = idx >> 6;
        int col = idx & 63;
        int hh = col >> 2;
        int q = col & 3;
        Ws[idx] = Whh[(size_t)(q * H_ + h0 + hh) * N_ + k];
    }

    int bg  = tid >> 4;               // 0..7
    int hid = tid & 15;               // 0..15
    float creg[4] = {0.f, 0.f, 0.f, 0.f};
    __syncthreads();

    for (int t = 0; t < T_; ++t) {
        unsigned long long accA[4], accB[4];   // (i,f) and (g,o) gate pairs
#pragma unroll
        for (int i = 0; i < 4; ++i) {
            int b = b0 + bg * 4 + i;
            const float* g1 = g_G1 + ((size_t)t * B_ + b) * G_ + h0 + hid;
            accA[i] = pk2(__ldcg(g1 + 0),   __ldcg(g1 + 256));
            accB[i] = pk2(__ldcg(g1 + 512), __ldcg(g1 + 768));
        }

        const float4* gh4 = (const float4*)g_hbuf[t & 1];
#pragma unroll
        for (int it = 0; it < 16; ++it) {
            int idx = tid + it * 128;         // 0..2047
            int k = idx >> 3;
            int j = idx & 7;
            float4 v = __ldcg(gh4 + k * 64 + (b0 >> 2) + j);
            Hs4[k * 16 + j * 2]     = make_float4(v.x, v.x, v.y, v.y);
            Hs4[k * 16 + j * 2 + 1] = make_float4(v.z, v.z, v.w, v.w);
        }
        __syncthreads();

        const ulonglong2* wp = Ws2 + hid;
        const ulonglong2* hp = Hs2 + bg * 2;
#pragma unroll 8
        for (int k = 0; k < 256; ++k) {
            ulonglong2 w   = wp[k * 16];      // (w_i,w_f),(w_g,w_o)
            ulonglong2 h01 = hp[k * 16];      // (h0,h0),(h1,h1)
            ulonglong2 h23 = hp[k * 16 + 1];  // (h2,h2),(h3,h3)
            FMA2(accA[0], h01.x, w.x); FMA2(accB[0], h01.x, w.y);
            FMA2(accA[1], h01.y, w.x); FMA2(accB[1], h01.y, w.y);
            FMA2(accA[2], h23.x, w.x); FMA2(accB[2], h23.x, w.y);
            FMA2(accA[3], h23.y, w.x); FMA2(accB[3], h23.y, w.y);
        }

        float* ghw = g_hbuf[(t + 1) & 1];
#pragma unroll
        for (int i = 0; i < 4; ++i) {
            int b = b0 + bg * 4 + i;
            float gi, gf, gg, go;
            upk2(accA[i], gi, gf);
            upk2(accB[i], gg, go);
            float ig = sigf(gi);
            float fg = sigf(gf);
            float g_ = tanhfast(gg);
            float og = sigf(go);
            float c = fmaf(fg, creg[i], ig * g_);
            creg[i] = c;
            float hn = og * tanhfast(c);
            __stcg(&ghw[(h0 + hid) * B_ + b], hn);
            out_enc[((size_t)b * T_ + t) * H_ + h0 + hid] = hn;
        }

        if (t + 1 < T_) grid_sync();
    }
}

// ---------------- launch ----------------
extern "C" void kernel_launch(void* const* d_in, const int* in_sizes, int n_in,
                              void* d_out, int out_size) {
    const float* input  = (const float*)d_in[0];
    const float* W_ih   = (const float*)d_in[1];
    const float* W_hh   = (const float*)d_in[2];
    const float* b_ih   = (const float*)d_in[3];
    const float* b_hh   = (const float*)d_in[4];
    const float* attn_w = (const float*)d_in[5];
    float* out = (float*)d_out;

    cudaFuncSetAttribute(k_recur, cudaFuncAttributeMaxDynamicSharedMemorySize, 131072);

    // K1: attention weights (+ zero h state)
    k_attn<<<B_, N_>>>(input, attn_w);
    // K2: weighted input -> output region 0 + bf16 hi/lo staging
    k_weighted<<<B_ * T_, N_>>>(input, out);
    // K2b: W_ih bf16 hi/lo
    k_convB<<<G_, N_>>>(W_ih);
    // K3: HMMA split-bf16 GEMM into g_G1
    dim3 g3(8, 1024);
    k_gemm_mma<<<g3, 256>>>(b_ih, b_hh);
    // K4: persistent recurrence -> output region 1 (proven global barrier)
    dim3 g4(8, 16);
    k_recur<<<g4, 128, 131072>>>(W_hh, out + ENC_OFF);
}

// round 7
// speedup vs baseline: 1.7690x; 1.0278x over previous
#include <cuda_runtime.h>
#include <cuda_bf16.h>
#include <cstdint>

// Problem constants
#define B_ 256
#define T_ 512          // TM1
#define N_ 256
#define H_ 256
#define G_ 1024         // 4*H
#define ENC_OFF ((size_t)B_ * T_ * N_)   // offset of input_encoded in d_out

// ---------------- device scratch (no cudaMalloc allowed) ----------------
__device__ float g_attn[B_ * N_];                      // softmax(x_scores)
__device__ float g_G1[(size_t)T_ * B_ * G_];           // gates pre-recurrence, [m=t*B+b][j]
__device__ float g_hbuf[2][H_ * B_];                   // ping-pong hidden state, [h][b]
__device__ __nv_bfloat16 g_Ahi[(size_t)T_ * B_ * N_];  // weighted, bf16 hi
__device__ __nv_bfloat16 g_Alo[(size_t)T_ * B_ * N_];  // weighted, bf16 lo
__device__ __nv_bfloat16 g_Bhi[G_ * N_];               // W_ih, bf16 hi
__device__ __nv_bfloat16 g_Blo[G_ * N_];               // W_ih, bf16 lo
__device__ unsigned g_cnt_leaf[8];                     // tree barrier leaves
__device__ unsigned g_cnt_root;                        // tree barrier root
__device__ volatile unsigned g_gen;                    // global generation

// ---------------- packed fp32x2 helpers ----------------
#define FMA2(d, a, b) asm("fma.rn.f32x2 %0, %1, %2, %0;" : "+l"(d) : "l"(a), "l"(b))

__device__ __forceinline__ unsigned long long pk2(float lo, float hi) {
    unsigned long long r;
    asm("mov.b64 %0, {%1, %2};" : "=l"(r) : "f"(lo), "f"(hi));
    return r;
}
__device__ __forceinline__ void upk2(unsigned long long v, float& lo, float& hi) {
    asm("mov.b64 {%0, %1}, %2;" : "=f"(lo), "=f"(hi) : "l"(v));
}
__device__ __forceinline__ float sigf(float x) {
    return __fdividef(1.f, 1.f + __expf(-x));
}
__device__ __forceinline__ float tanhfast(float x) {
    return __fdividef(2.f, 1.f + __expf(-2.f * x)) - 1.f;
}
__device__ __forceinline__ uint32_t smem_to_u32(const void* p) {
    uint32_t a;
    asm("{ .reg .u64 t; cvta.to.shared.u64 t, %1; cvt.u32.u64 %0, t; }" : "=r"(a) : "l"(p));
    return a;
}

// ---------------- cp.async helpers ----------------
#define CP_ASYNC16(dst, src) \
    asm volatile("cp.async.cg.shared.global [%0], [%1], 16;" :: "r"(dst), "l"(src) : "memory")
#define CP_COMMIT() asm volatile("cp.async.commit_group;" ::: "memory")
#define CP_WAIT1() asm volatile("cp.async.wait_group 1;" ::: "memory")
#define CP_WAIT0() asm volatile("cp.async.wait_group 0;" ::: "memory")

// ---------------- K1: x_scores + softmax -> attn, zero h buffer ----------------
__global__ void k_attn(const float* __restrict__ in, const float* __restrict__ attn_w) {
    __shared__ float wx[T_];
    __shared__ float red[N_];
    int b = blockIdx.x;
    int n = threadIdx.x;

    wx[n]       = attn_w[2 * H_ + n];
    wx[n + 256] = attn_w[2 * H_ + 256 + n];
    __syncthreads();

    const float* p = in + (size_t)b * T_ * N_ + n;
    float acc = 0.f;
#pragma unroll 8
    for (int t = 0; t < T_; ++t)
        acc = fmaf(p[(size_t)t * N_], wx[t], acc);

    red[n] = acc;
    __syncthreads();
    for (int s = 128; s > 0; s >>= 1) {
        if (n < s) red[n] = fmaxf(red[n], red[n + s]);
        __syncthreads();
    }
    float mx = red[0];
    __syncthreads();
    float e = expf(acc - mx);
    red[n] = e;
    __syncthreads();
    for (int s = 128; s > 0; s >>= 1) {
        if (n < s) red[n] += red[n + s];
        __syncthreads();
    }
    g_attn[b * N_ + n] = e / red[0];
    g_hbuf[0][b * N_ + n] = 0.f;
}

// ---------------- K2: weighted = attn * x -> out region 0 + bf16 hi/lo ---------
__global__ void k_weighted(const float* __restrict__ in, float* __restrict__ out) {
    int blk = blockIdx.x;            // b*T_ + t
    int b = blk >> 9;
    int t = blk & 511;
    int n = threadIdx.x;
    size_t idx = (size_t)blk * N_ + n;
    float w = g_attn[b * N_ + n] * in[idx];
    out[idx] = w;
    size_t m = (size_t)t * B_ + b;   // GEMM row index
    __nv_bfloat16 hi = __float2bfloat16(w);
    __nv_bfloat16 lo = __float2bfloat16(w - __bfloat162float(hi));
    g_Ahi[m * N_ + n] = hi;
    g_Alo[m * N_ + n] = lo;
}

// ---------------- K2b: W_ih -> bf16 hi/lo ----------------
__global__ void k_convB(const float* __restrict__ Wih) {
    int j = blockIdx.x;
    int k = threadIdx.x;
    float v = Wih[(size_t)j * N_ + k];
    __nv_bfloat16 hi = __float2bfloat16(v);
    __nv_bfloat16 lo = __float2bfloat16(v - __bfloat162float(hi));
    g_Bhi[j * N_ + k] = hi;
    g_Blo[j * N_ + k] = lo;
}

// ---------------- K3: mma.sync bf16 split GEMM, cp.async double-buffered -------
// D[128m x 128n] per CTA; effective K = 768 = 3 terms x 256:
//   term0: Ahi*Bhi, term1: Alo*Bhi, term2: Ahi*Blo   (lo*lo dropped)
// 8 warps as 2(m) x 4(n); warp tile 64x32; m16n8k16 HMMA.
#define LDM_X4(r0, r1, r2, r3, a) \
    asm volatile("ldmatrix.sync.aligned.m8n8.x4.shared.b16 {%0,%1,%2,%3}, [%4];" \
                 : "=r"(r0), "=r"(r1), "=r"(r2), "=r"(r3) : "r"(a))
#define MMA16816(c, a, b) \
    asm volatile("mma.sync.aligned.m16n8k16.row.col.f32.bf16.bf16.f32 " \
                 "{%0,%1,%2,%3}, {%4,%5,%6,%7}, {%8,%9}, {%0,%1,%2,%3};" \
                 : "+f"((c)[0]), "+f"((c)[1]), "+f"((c)[2]), "+f"((c)[3]) \
                 : "r"((a)[0]), "r"((a)[1]), "r"((a)[2]), "r"((a)[3]), "r"((b)[0]), "r"((b)[1]))

#define TILE_BYTES 16384           // 128 x 64 bf16
// SMEM layout: As0 | Bs0 | As1 | Bs1   (each 16 KB)

__global__ void __launch_bounds__(256) k_gemm_mma(
        const float* __restrict__ b_ih, const float* __restrict__ b_hh) {
    __shared__ __align__(16) __nv_bfloat16 Sb[4 * 128 * 64];   // 64 KB
    __shared__ float bias_s[128];

    int tid = threadIdx.x;
    int wid = tid >> 5;
    int lane = tid & 31;
    int nt = blockIdx.x;             // 0..7  gate tile
    int mt = blockIdx.y;             // 0..1023 m tile
    int j0 = nt * 128;
    int wm = wid >> 2;               // 0..1
    int wn = wid & 3;                // 0..3

    if (tid < 128) bias_s[tid] = b_ih[j0 + tid] + b_hh[j0 + tid];

    uint32_t s_base = smem_to_u32(Sb);

    // staging indices (per thread, 4 iterations, 16B each, for A and B)
    int st_r[4], st_sw[4];
#pragma unroll
    for (int it = 0; it < 4; ++it) {
        int idx = tid + it * 256;        // 0..1023
        int r = idx >> 3;
        int kg = idx & 7;
        st_r[it] = r * 32 + kg;          // gmem uint4 index (row-major 256-col)
        st_sw[it] = r * 8 + (kg ^ (r & 7));  // smem uint4 index (swizzled)
    }

    const __nv_bfloat16* a_srcs[3] = {g_Ahi, g_Alo, g_Ahi};
    const __nv_bfloat16* b_srcs[3] = {g_Bhi, g_Bhi, g_Blo};

    // issue chunk: term = ch>>2, kk0 = (ch&3)*64, into stage buffer s = ch&1
#define ISSUE_CHUNK(ch) do { \
        int _term = (ch) >> 2; \
        int _kk0 = ((ch) & 3) * 64; \
        const char* _gA = (const char*)(a_srcs[_term] + (size_t)mt * 128 * N_ + _kk0); \
        const char* _gB = (const char*)(b_srcs[_term] + (size_t)j0 * N_ + _kk0); \
        uint32_t _sa = s_base + ((ch) & 1) * 2u * TILE_BYTES; \
        uint32_t _sb = _sa + TILE_BYTES; \
        _Pragma("unroll") \
        for (int _it = 0; _it < 4; ++_it) { \
            CP_ASYNC16(_sa + (uint32_t)st_sw[_it] * 16u, _gA + (size_t)st_r[_it] * 16); \
            CP_ASYNC16(_sb + (uint32_t)st_sw[_it] * 16u, _gB + (size_t)st_r[_it] * 16); \
        } \
        CP_COMMIT(); \
    } while (0)

    // ldmatrix lane-dependent precomputation
    int a_r15 = lane & 15;                 // row within 16-tile
    int a_kh  = lane >> 4;                 // 0/1 -> k half
    int b_row = ((lane & 16) >> 1) + (lane & 7);   // 16 n-rows across lane quads
    int b_kh  = (lane >> 3) & 1;           // 0/1 -> k half

    float acc[4][4][4];
#pragma unroll
    for (int i = 0; i < 4; ++i)
#pragma unroll
        for (int j = 0; j < 4; ++j)
#pragma unroll
            for (int q = 0; q < 4; ++q) acc[i][j][q] = 0.f;

    ISSUE_CHUNK(0);

    for (int ch = 0; ch < 12; ++ch) {
        if (ch + 1 < 12) {
            ISSUE_CHUNK(ch + 1);
            CP_WAIT1();
        } else {
            CP_WAIT0();
        }
        __syncthreads();

        uint32_t as_base = s_base + (ch & 1) * 2u * TILE_BYTES;
        uint32_t bs_base = as_base + TILE_BYTES;

#pragma unroll
        for (int ks = 0; ks < 4; ++ks) {
            uint32_t afr[4][4];
            uint32_t bfr[4][2];
#pragma unroll
            for (int tm = 0; tm < 4; ++tm) {
                int row = wm * 64 + tm * 16 + a_r15;
                int c = (2 * ks + a_kh) ^ (a_r15 & 7);
                uint32_t addr = as_base + (uint32_t)(row * 64 + c * 8) * 2u;
                LDM_X4(afr[tm][0], afr[tm][1], afr[tm][2], afr[tm][3], addr);
            }
#pragma unroll
            for (int tn2 = 0; tn2 < 2; ++tn2) {
                int row = wn * 32 + tn2 * 16 + b_row;
                int c = (2 * ks + b_kh) ^ (b_row & 7);
                uint32_t addr = bs_base + (uint32_t)(row * 64 + c * 8) * 2u;
                uint32_t r0, r1, r2, r3;
                LDM_X4(r0, r1, r2, r3, addr);
                bfr[tn2 * 2 + 0][0] = r0; bfr[tn2 * 2 + 0][1] = r1;
                bfr[tn2 * 2 + 1][0] = r2; bfr[tn2 * 2 + 1][1] = r3;
            }
#pragma unroll
            for (int tm = 0; tm < 4; ++tm)
#pragma unroll
                for (int tn = 0; tn < 4; ++tn)
                    MMA16816(acc[tm][tn], afr[tm], bfr[tn]);
        }
        __syncthreads();
    }

    // epilogue: add bias, write g_G1
    int qr = lane >> 2;              // 0..7 row-in-8
    int qc = (lane & 3) * 2;         // col pair base
#pragma unroll
    for (int tm = 0; tm < 4; ++tm) {
#pragma unroll
        for (int tn = 0; tn < 4; ++tn) {
            int colt = wn * 32 + tn * 8 + qc;       // 0..127 within tile
            size_t m0 = (size_t)mt * 128 + wm * 64 + tm * 16 + qr;
            float bx = bias_s[colt], by = bias_s[colt + 1];
            float2 v0 = make_float2(acc[tm][tn][0] + bx, acc[tm][tn][1] + by);
            float2 v1 = make_float2(acc[tm][tn][2] + bx, acc[tm][tn][3] + by);
            *(float2*)(g_G1 + m0 * G_ + j0 + colt) = v0;
            *(float2*)(g_G1 + (m0 + 8) * G_ + j0 + colt) = v1;
        }
    }
}

// ---------------- K4: persistent recurrence ----------------
// Tree barrier with GLOBAL semantics: 8 leaves x 16 arrivals -> root x 8 -> gen.
__device__ __forceinline__ void grid_sync_tree(int leaf) {
    __threadfence();
    __syncthreads();
    if (threadIdx.x == 0) {
        unsigned gen = g_gen;
        if (atomicAdd(&g_cnt_leaf[leaf], 1u) == 15u) {
            g_cnt_leaf[leaf] = 0;
            if (atomicAdd(&g_cnt_root, 1u) == 7u) {
                g_cnt_root = 0;
                __threadfence();
                g_gen = gen + 1u;
            }
        }
        while (g_gen == gen) { __nanosleep(64); }
        __threadfence();
    }
    __syncthreads();
}

__global__ void __launch_bounds__(128, 1) k_recur(
        const float* __restrict__ Whh, float* __restrict__ out_enc) {
    extern __shared__ float sm[];
    float* Ws = sm;                   // 16384 floats
    float* Hs = sm + 16384;           // 16384 floats (duplicated h)
    const ulonglong2* Ws2 = (const ulonglong2*)Ws;
    const ulonglong2* Hs2 = (const ulonglong2*)Hs;
    float4* Hs4 = (float4*)Hs;

    int tid = threadIdx.x;            // 128
    int b0  = blockIdx.x * 32;
    int h0  = blockIdx.y * 16;
    int leaf = blockIdx.x;

    for (int idx = tid; idx < 16384; idx += 128) {
        int k = idx >> 6;
        int col = idx & 63;
        int hh = col >> 2;
        int q = col & 3;
        Ws[idx] = Whh[(size_t)(q * H_ + h0 + hh) * N_ + k];
    }

    int bg  = tid >> 4;               // 0..7
    int hid = tid & 15;               // 0..15
    float creg[4] = {0.f, 0.f, 0.f, 0.f};
    __syncthreads();

    // prefetch acc for t=0 (G1 is static; latency overlaps other CTAs' startup)
    unsigned long long accA[4], accB[4];   // (i,f) and (g,o) gate pairs
#pragma unroll
    for (int i = 0; i < 4; ++i) {
        int b = b0 + bg * 4 + i;
        const float* g1 = g_G1 + ((size_t)b) * G_ + h0 + hid;
        accA[i] = pk2(__ldcg(g1 + 0),   __ldcg(g1 + 256));
        accB[i] = pk2(__ldcg(g1 + 512), __ldcg(g1 + 768));
    }

    for (int t = 0; t < T_; ++t) {
        // stage this CTA's h slice [256 k][32 b] DUPLICATED for FMA2
        const float4* gh4 = (const float4*)g_hbuf[t & 1];
#pragma unroll
        for (int it = 0; it < 16; ++it) {
            int idx = tid + it * 128;         // 0..2047
            int k = idx >> 3;
            int j = idx & 7;
            float4 v = __ldcg(gh4 + k * 64 + (b0 >> 2) + j);
            Hs4[k * 16 + j * 2]     = make_float4(v.x, v.x, v.y, v.y);
            Hs4[k * 16 + j * 2 + 1] = make_float4(v.z, v.z, v.w, v.w);
        }
        __syncthreads();

        const ulonglong2* wp = Ws2 + hid;
        const ulonglong2* hp = Hs2 + bg * 2;
#pragma unroll 8
        for (int k = 0; k < 256; ++k) {
            ulonglong2 w   = wp[k * 16];      // (w_i,w_f),(w_g,w_o)
            ulonglong2 h01 = hp[k * 16];      // (h0,h0),(h1,h1)
            ulonglong2 h23 = hp[k * 16 + 1];  // (h2,h2),(h3,h3)
            FMA2(accA[0], h01.x, w.x); FMA2(accB[0], h01.x, w.y);
            FMA2(accA[1], h01.y, w.x); FMA2(accB[1], h01.y, w.y);
            FMA2(accA[2], h23.x, w.x); FMA2(accB[2], h23.x, w.y);
            FMA2(accA[3], h23.y, w.x); FMA2(accB[3], h23.y, w.y);
        }

        // fused LSTM cell update + output store
        float* ghw = g_hbuf[(t + 1) & 1];
#pragma unroll
        for (int i = 0; i < 4; ++i) {
            int b = b0 + bg * 4 + i;
            float gi, gf, gg, go;
            upk2(accA[i], gi, gf);
            upk2(accB[i], gg, go);
            float ig = sigf(gi);
            float fg = sigf(gf);
            float g_ = tanhfast(gg);
            float og = sigf(go);
            float c = fmaf(fg, creg[i], ig * g_);
            creg[i] = c;
            float hn = og * tanhfast(c);
            __stcg(&ghw[(h0 + hid) * B_ + b], hn);
            out_enc[((size_t)b * T_ + t) * H_ + h0 + hid] = hn;
        }

        if (t + 1 < T_) {
            // prefetch acc for step t+1 BEFORE the barrier (hides DRAM latency)
#pragma unroll
            for (int i = 0; i < 4; ++i) {
                int b = b0 + bg * 4 + i;
                const float* g1 = g_G1 + ((size_t)(t + 1) * B_ + b) * G_ + h0 + hid;
                accA[i] = pk2(__ldcg(g1 + 0),   __ldcg(g1 + 256));
                accB[i] = pk2(__ldcg(g1 + 512), __ldcg(g1 + 768));
            }
            grid_sync_tree(leaf);
        }
    }
}

// ---------------- launch ----------------
extern "C" void kernel_launch(void* const* d_in, const int* in_sizes, int n_in,
                              void* d_out, int out_size) {
    const float* input  = (const float*)d_in[0];
    const float* W_ih   = (const float*)d_in[1];
    const float* W_hh   = (const float*)d_in[2];
    const float* b_ih   = (const float*)d_in[3];
    const float* b_hh   = (const float*)d_in[4];
    const float* attn_w = (const float*)d_in[5];
    float* out = (float*)d_out;

    cudaFuncSetAttribute(k_recur, cudaFuncAttributeMaxDynamicSharedMemorySize, 131072);

    // K1: attention weights (+ zero h state)
    k_attn<<<B_, N_>>>(input, attn_w);
    // K2: weighted input -> output region 0 + bf16 hi/lo staging
    k_weighted<<<B_ * T_, N_>>>(input, out);
    // K2b: W_ih bf16 hi/lo
    k_convB<<<G_, N_>>>(W_ih);
    // K3: HMMA split-bf16 GEMM into g_G1, cp.async double-buffered
    dim3 g3(8, 1024);
    k_gemm_mma<<<g3, 256>>>(b_ih, b_hh);
    // K4: persistent recurrence -> output region 1 (tree barrier, global semantics)
    dim3 g4(8, 16);
    k_recur<<<g4, 128, 131072>>>(W_hh, out + ENC_OFF);
}